// round 1
// baseline (speedup 1.0000x reference)
#include <cuda_runtime.h>
#include <cuda_bf16.h>
#include <cstdint>

#define NV 100000      // vertices
#define ME 50000       // hyperedges
#define KH 8           // hyperedge size
#define DD 128         // feature dim (in == out)

// ---------------- scratch (no allocs allowed) ----------------
__device__ float g_Y  [(size_t)NV * DD];   // X@W + b
__device__ float g_Xs [(size_t)NV * DD];   // Y * dinv
__device__ float g_deg [NV];
__device__ float g_dinv[NV];
__device__ int   g_u  [ME];
__device__ int   g_v  [ME];
__device__ int   g_pos[ME];                // ui | (vi<<8)

// ---------------- helpers ----------------
__device__ __forceinline__ void red4(float* p, float a, float b, float c, float d) {
    asm volatile("red.global.add.v4.f32 [%0], {%1,%2,%3,%4};"
                 :: "l"(p), "f"(a), "f"(b), "f"(c), "f"(d) : "memory");
}

// ---------------- K0: deg = 1 ----------------
__global__ void k_init_deg() {
    int n = blockIdx.x * blockDim.x + threadIdx.x;
    if (n < NV) g_deg[n] = 1.0f;
}

// ---------------- K1: Y = X @ W + b  (fp32, 64x128 block tile) ----------------
__global__ __launch_bounds__(256) void k_gemm(const float* __restrict__ X,
                                              const float* __restrict__ W,
                                              const float* __restrict__ b) {
    __shared__ float Wsh[32][128];
    __shared__ float Xsh[64][32];

    const int tid = threadIdx.x;
    const int cg  = tid & 31;     // col group: cols [4cg, 4cg+4)
    const int rg  = tid >> 5;     // row group: rows [8rg, 8rg+8)
    const int row0 = blockIdx.x * 64;

    float acc[8][4];
    const float4 bv = *reinterpret_cast<const float4*>(b + cg * 4);
    #pragma unroll
    for (int r = 0; r < 8; ++r) {
        acc[r][0] = bv.x; acc[r][1] = bv.y; acc[r][2] = bv.z; acc[r][3] = bv.w;
    }

    for (int kt = 0; kt < 4; ++kt) {
        // load W tile 32x128
        #pragma unroll
        for (int i = 0; i < 4; ++i) {
            int f  = tid + i * 256;          // float4 index 0..1023
            int kr = f >> 5, c4 = f & 31;
            *reinterpret_cast<float4*>(&Wsh[kr][c4 * 4]) =
                *reinterpret_cast<const float4*>(W + (size_t)(kt * 32 + kr) * 128 + c4 * 4);
        }
        // load X tile 64x32
        #pragma unroll
        for (int i = 0; i < 2; ++i) {
            int f = tid + i * 256;           // float4 index 0..511
            int r = f >> 3, c4 = f & 7;
            int grow = row0 + r;
            float4 xv = make_float4(0.f, 0.f, 0.f, 0.f);
            if (grow < NV)
                xv = *reinterpret_cast<const float4*>(X + (size_t)grow * 128 + kt * 32 + c4 * 4);
            *reinterpret_cast<float4*>(&Xsh[r][c4 * 4]) = xv;
        }
        __syncthreads();

        #pragma unroll
        for (int k = 0; k < 32; ++k) {
            const float4 wv = *reinterpret_cast<const float4*>(&Wsh[k][cg * 4]);
            #pragma unroll
            for (int r = 0; r < 8; ++r) {
                const float xv = Xsh[rg * 8 + r][k];
                acc[r][0] += xv * wv.x;
                acc[r][1] += xv * wv.y;
                acc[r][2] += xv * wv.z;
                acc[r][3] += xv * wv.w;
            }
        }
        __syncthreads();
    }

    #pragma unroll
    for (int r = 0; r < 8; ++r) {
        int grow = row0 + rg * 8 + r;
        if (grow < NV)
            *reinterpret_cast<float4*>(g_Y + (size_t)grow * 128 + cg * 4) =
                make_float4(acc[r][0], acc[r][1], acc[r][2], acc[r][3]);
    }
}

// ---------------- K2: per-hyperedge argmax pair + degree atomics ----------------
__global__ __launch_bounds__(256) void k_edges(const int* __restrict__ vertex) {
    const int warp = (blockIdx.x * 256 + threadIdx.x) >> 5;
    const int lane = threadIdx.x & 31;
    if (warp >= ME) return;
    const unsigned FULL = 0xffffffffu;

    int vr = (lane < KH) ? vertex[warp * KH + lane] : 0;
    int verts[KH];
    #pragma unroll
    for (int i = 0; i < KH; ++i) verts[i] = __shfl_sync(FULL, vr, i);

    // gather 8 rows of Y: lane handles dims [4*lane, 4*lane+4)
    float4 f[KH];
    #pragma unroll
    for (int k = 0; k < KH; ++k)
        f[k] = *reinterpret_cast<const float4*>(g_Y + (size_t)verts[k] * DD + lane * 4);

    // 36 unique pair partial dots (k<=l), then warp allreduce
    float p[36];
    {
        int idx = 0;
        #pragma unroll
        for (int k = 0; k < KH; ++k)
            #pragma unroll
            for (int l = k; l < KH; ++l) {
                p[idx++] = f[k].x * f[l].x + f[k].y * f[l].y +
                           f[k].z * f[l].z + f[k].w * f[l].w;
            }
    }
    #pragma unroll
    for (int i = 0; i < 36; ++i) {
        #pragma unroll
        for (int s = 16; s > 0; s >>= 1)
            p[i] += __shfl_xor_sync(FULL, p[i], s);
    }

    const int off[8] = {0, 8, 15, 21, 26, 30, 33, 35};   // pidx(k,k)
    float sq[KH];
    #pragma unroll
    for (int k = 0; k < KH; ++k) sq[k] = p[off[k]];

    // flat row-major argmax with strict > (first occurrence == jnp.argmax)
    float best = -3.4e38f;
    int bi = 0;
    #pragma unroll
    for (int k = 0; k < KH; ++k) {
        #pragma unroll
        for (int l = 0; l < KH; ++l) {
            const int kk = (k < l) ? k : l;
            const int ll = (k < l) ? l : k;
            const float dt = p[off[kk] + (ll - kk)];
            const float d2 = (sq[k] + sq[l]) - 2.0f * dt;
            if (d2 > best) { best = d2; bi = k * KH + l; }
        }
    }
    const int ui = bi >> 3, vi = bi & 7;
    const int u = verts[ui], v = verts[vi];

    if (lane == 0) {
        g_u[warp] = u;
        g_v[warp] = v;
        g_pos[warp] = ui | (vi << 8);
    }
    const float w = 1.0f / 13.0f;   // 1/(2K-3)
    if (lane < KH) {
        if (lane == ui)       atomicAdd(&g_deg[u], 7.0f * w);
        else if (lane == vi)  atomicAdd(&g_deg[v], 7.0f * w);
        else                  atomicAdd(&g_deg[verts[lane]], 2.0f * w);
    }
}

// ---------------- K3a: dinv ----------------
__global__ void k_dinv() {
    int n = blockIdx.x * blockDim.x + threadIdx.x;
    if (n < NV) g_dinv[n] = rsqrtf(g_deg[n]);
}

// ---------------- K3b: Xs = Y*dinv ; out = Xs ----------------
__global__ void k_scale(float* __restrict__ out) {
    int i = blockIdx.x * blockDim.x + threadIdx.x;   // float4 chunk idx
    if (i >= NV * 32) return;
    const int n = i >> 5;
    const float d = g_dinv[n];
    float4 y = *reinterpret_cast<const float4*>(g_Y + (size_t)i * 4);
    float4 xs = make_float4(y.x * d, y.y * d, y.z * d, y.w * d);
    *reinterpret_cast<float4*>(g_Xs + (size_t)i * 4) = xs;
    reinterpret_cast<float4*>(out)[i] = xs;
}

// ---------------- K4: feature scatter (folded, v4 red atomics) ----------------
__global__ __launch_bounds__(256) void k_scatter(const int* __restrict__ vertex,
                                                 float* __restrict__ out) {
    const int warp = (blockIdx.x * 256 + threadIdx.x) >> 5;
    const int lane = threadIdx.x & 31;
    if (warp >= ME) return;
    const unsigned FULL = 0xffffffffu;

    int vr = (lane < KH) ? vertex[warp * KH + lane] : 0;
    int verts[KH];
    #pragma unroll
    for (int i = 0; i < KH; ++i) verts[i] = __shfl_sync(FULL, vr, i);

    const int u = g_u[warp];
    const int v = g_v[warp];
    const int pos = g_pos[warp];
    const int ui = pos & 0xff, vi = (pos >> 8) & 0xff;
    const float w = 1.0f / 13.0f;

    const float4 xu = *reinterpret_cast<const float4*>(g_Xs + (size_t)u * DD + lane * 4);
    const float4 xv = *reinterpret_cast<const float4*>(g_Xs + (size_t)v * DD + lane * 4);

    // contribution to every mediator: w*(Xs[u] + Xs[v])
    const float tx = w * (xu.x + xv.x);
    const float ty = w * (xu.y + xv.y);
    const float tz = w * (xu.z + xv.z);
    const float tw = w * (xu.w + xv.w);

    float4 S = make_float4(0.f, 0.f, 0.f, 0.f);
    #pragma unroll
    for (int pidx = 0; pidx < KH; ++pidx) {
        if (pidx == ui || pidx == vi) continue;
        const int mv = verts[pidx];
        const float4 xm = *reinterpret_cast<const float4*>(g_Xs + (size_t)mv * DD + lane * 4);
        S.x += xm.x; S.y += xm.y; S.z += xm.z; S.w += xm.w;
        red4(out + (size_t)mv * DD + lane * 4, tx, ty, tz, tw);
    }
    // out[u] += w*(Xs[v] + sum_m Xs[m]) ; out[v] += w*(Xs[u] + sum_m Xs[m])
    red4(out + (size_t)u * DD + lane * 4,
         w * (xv.x + S.x), w * (xv.y + S.y), w * (xv.z + S.z), w * (xv.w + S.w));
    red4(out + (size_t)v * DD + lane * 4,
         w * (xu.x + S.x), w * (xu.y + S.y), w * (xu.z + S.z), w * (xu.w + S.w));
}

// ---------------- K5: out = relu(out * dinv) ----------------
__global__ void k_relu(float* __restrict__ out) {
    int i = blockIdx.x * blockDim.x + threadIdx.x;
    if (i >= NV * 32) return;
    const int n = i >> 5;
    const float d = g_dinv[n];
    float4 o = reinterpret_cast<float4*>(out)[i];
    o.x = fmaxf(o.x * d, 0.f);
    o.y = fmaxf(o.y * d, 0.f);
    o.z = fmaxf(o.z * d, 0.f);
    o.w = fmaxf(o.w * d, 0.f);
    reinterpret_cast<float4*>(out)[i] = o;
}

// ---------------- launch ----------------
extern "C" void kernel_launch(void* const* d_in, const int* in_sizes, int n_in,
                              void* d_out, int out_size) {
    const float* X      = (const float*)d_in[0];   // [N, 128]
    const int*   vertex = (const int*)  d_in[1];   // [M*8]
    // d_in[2] = edges (repeat(arange(M), 8)) — unused by the reference math
    const float* W      = (const float*)d_in[3];   // [128, 128]
    const float* b      = (const float*)d_in[4];   // [128]
    float* out = (float*)d_out;

    k_init_deg<<<(NV + 255) / 256, 256>>>();
    k_gemm<<<(NV + 63) / 64, 256>>>(X, W, b);
    k_edges<<<(ME * 32 + 255) / 256, 256>>>(vertex);
    k_dinv<<<(NV + 255) / 256, 256>>>();
    k_scale<<<(NV * 32 + 255) / 256, 256>>>(out);
    k_scatter<<<(ME * 32 + 255) / 256, 256>>>(vertex, out);
    k_relu<<<(NV * 32 + 255) / 256, 256>>>(out);
}

// round 3
// speedup vs baseline: 1.0732x; 1.0732x over previous
#include <cuda_runtime.h>
#include <cuda_fp16.h>
#include <cstdint>

#define NV 100000      // vertices
#define ME 50000       // hyperedges
#define KH 8           // hyperedge size
#define DD 128         // feature dim
#define ASTRIDE 136    // smem A/stage row stride (in halves / floats)

// ---------------- scratch (no allocs allowed) ----------------
__device__ float  g_Y  [(size_t)NV * DD];   // X@W + b
__device__ float  g_deg [NV];
__device__ float  g_dinv[NV];
__device__ int    g_pos[ME];                // ui | (vi<<8)
__device__ __half g_Wph[16384];             // W hi, mma B-fragment layout
__device__ __half g_Wpl[16384];             // W lo, mma B-fragment layout

__device__ __forceinline__ void red4(float* p, float a, float b, float c, float d) {
    asm volatile("red.global.add.v4.f32 [%0], {%1,%2,%3,%4};"
                 :: "l"(p), "f"(a), "f"(b), "f"(c), "f"(d) : "memory");
}
__device__ __forceinline__ uint32_t pk2(__half a, __half b) {
    __half2 t = __halves2half2(a, b);
    return *reinterpret_cast<uint32_t*>(&t);
}

// ---------------- K_pre: deg=1 ; pack W into fp16 hi/lo B-fragment layout ----------------
__global__ void k_pre(const float* __restrict__ W) {
    int t = blockIdx.x * blockDim.x + threadIdx.x;
    if (t < NV) g_deg[t] = 1.0f;
    if (t < 16384) {
        int k = t >> 7, n = t & 127;          // W[k][n]
        float w = W[t];
        __half wh = __float2half_rn(w);
        __half wl = __float2half_rn(w - __half2float(wh));
        int s = k >> 4, kr = k & 15;          // kstep, k within step
        int r = kr >> 3;                      // b-frag reg index (0/1)
        int lane = ((n & 7) << 2) | ((kr & 7) >> 1);
        int j = n >> 3;                       // n-tile
        int idx = ((((s * 16 + j) * 32 + lane) * 2 + r) << 1) | (kr & 1);
        g_Wph[idx] = wh;
        g_Wpl[idx] = wl;
    }
}

// ---------------- K1: Y = X@W + b via fp16-split mma.sync (3 passes) ----------------
#define SMEM_SZ (512 + 128 * ASTRIDE * 2 * 2)   // bias + Ah + Al  (stage aliases Ah/Al)

__global__ __launch_bounds__(256) void k_gemm(const float* __restrict__ X,
                                              const float* __restrict__ b) {
    extern __shared__ char smem[];
    float*  bsm   = reinterpret_cast<float*>(smem);            // 128 floats
    __half* Ah    = reinterpret_cast<__half*>(smem + 512);     // 128 x ASTRIDE halves
    __half* Al    = Ah + 128 * ASTRIDE;
    float*  stage = reinterpret_cast<float*>(smem + 512);      // aliases A (epilogue)

    const int tid  = threadIdx.x;
    const int row0 = blockIdx.x * 128;
    if (tid < 128) bsm[tid] = b[tid];

    // load X tile coalesced, split fp16 hi/lo into smem
    #pragma unroll
    for (int i = 0; i < 16; ++i) {
        int f4  = tid + i * 256;              // 0..4095
        int row = f4 >> 5;
        int c   = f4 & 31;                    // float4 within row
        float4 x = make_float4(0.f, 0.f, 0.f, 0.f);
        if (row0 + row < NV)
            x = reinterpret_cast<const float4*>(X + (size_t)(row0 + row) * 128)[c];
        __half hx = __float2half_rn(x.x), hy = __float2half_rn(x.y);
        __half hz = __float2half_rn(x.z), hw = __float2half_rn(x.w);
        *reinterpret_cast<uint2*>(&Ah[row * ASTRIDE + c * 4]) =
            make_uint2(pk2(hx, hy), pk2(hz, hw));
        *reinterpret_cast<uint2*>(&Al[row * ASTRIDE + c * 4]) =
            make_uint2(pk2(__float2half_rn(x.x - __half2float(hx)),
                           __float2half_rn(x.y - __half2float(hy))),
                       pk2(__float2half_rn(x.z - __half2float(hz)),
                           __float2half_rn(x.w - __half2float(hw))));
    }
    __syncthreads();

    const int wid = tid >> 5, lane = tid & 31;
    const int m0 = wid * 16;
    const int rr = lane >> 2, kc = lane & 3;

    float acc[16][4];
    #pragma unroll
    for (int j = 0; j < 16; ++j)
        acc[j][0] = acc[j][1] = acc[j][2] = acc[j][3] = 0.f;

    #pragma unroll 1
    for (int pass = 0; pass < 3; ++pass) {
        const __half* A = (pass == 2) ? Al : Ah;
        const uint2*  B = reinterpret_cast<const uint2*>((pass == 1) ? g_Wpl : g_Wph);
        #pragma unroll
        for (int s = 0; s < 8; ++s) {
            const int ka = s * 16 + kc * 2;
            uint32_t a0 = *reinterpret_cast<const uint32_t*>(&A[(m0 + rr)     * ASTRIDE + ka]);
            uint32_t a1 = *reinterpret_cast<const uint32_t*>(&A[(m0 + rr + 8) * ASTRIDE + ka]);
            uint32_t a2 = *reinterpret_cast<const uint32_t*>(&A[(m0 + rr)     * ASTRIDE + ka + 8]);
            uint32_t a3 = *reinterpret_cast<const uint32_t*>(&A[(m0 + rr + 8) * ASTRIDE + ka + 8]);
            #pragma unroll
            for (int j = 0; j < 16; ++j) {
                uint2 bb = __ldg(&B[(s * 16 + j) * 32 + lane]);
                asm volatile(
                    "mma.sync.aligned.m16n8k16.row.col.f32.f16.f16.f32 "
                    "{%0,%1,%2,%3}, {%4,%5,%6,%7}, {%8,%9}, {%0,%1,%2,%3};"
                    : "+f"(acc[j][0]), "+f"(acc[j][1]), "+f"(acc[j][2]), "+f"(acc[j][3])
                    : "r"(a0), "r"(a1), "r"(a2), "r"(a3), "r"(bb.x), "r"(bb.y));
            }
        }
    }
    __syncthreads();   // A tiles dead; smem becomes stage

    // stage (+bias), then coalesced STG
    #pragma unroll
    for (int j = 0; j < 16; ++j) {
        const int n0 = j * 8 + kc * 2;
        const float b0 = bsm[n0], b1 = bsm[n0 + 1];
        *reinterpret_cast<float2*>(&stage[(m0 + rr)     * ASTRIDE + n0]) =
            make_float2(acc[j][0] + b0, acc[j][1] + b1);
        *reinterpret_cast<float2*>(&stage[(m0 + rr + 8) * ASTRIDE + n0]) =
            make_float2(acc[j][2] + b0, acc[j][3] + b1);
    }
    __syncthreads();
    #pragma unroll
    for (int s2 = 0; s2 < 16; ++s2) {
        int f  = tid + s2 * 256;              // 0..4095 float4
        int r2 = f >> 5, c2 = f & 31;
        if (row0 + r2 < NV) {
            float4 v = *reinterpret_cast<const float4*>(&stage[r2 * ASTRIDE + c2 * 4]);
            *reinterpret_cast<float4*>(g_Y + (size_t)(row0 + r2) * 128 + c2 * 4) = v;
        }
    }
}

// ---------------- K2: per-hyperedge argmax pair + degree atomics ----------------
__global__ __launch_bounds__(256) void k_edges(const int* __restrict__ vertex) {
    const int warp = (blockIdx.x * 256 + threadIdx.x) >> 5;
    const int lane = threadIdx.x & 31;
    if (warp >= ME) return;
    const unsigned FULL = 0xffffffffu;

    int vr = (lane < KH) ? vertex[warp * KH + lane] : 0;
    int verts[KH];
    #pragma unroll
    for (int i = 0; i < KH; ++i) verts[i] = __shfl_sync(FULL, vr, i);

    float4 f[KH];
    #pragma unroll
    for (int k = 0; k < KH; ++k)
        f[k] = *reinterpret_cast<const float4*>(g_Y + (size_t)verts[k] * DD + lane * 4);

    float p[36];
    {
        int idx = 0;
        #pragma unroll
        for (int k = 0; k < KH; ++k)
            #pragma unroll
            for (int l = k; l < KH; ++l)
                p[idx++] = f[k].x * f[l].x + f[k].y * f[l].y +
                           f[k].z * f[l].z + f[k].w * f[l].w;
    }
    #pragma unroll
    for (int i = 0; i < 36; ++i) {
        #pragma unroll
        for (int s = 16; s > 0; s >>= 1)
            p[i] += __shfl_xor_sync(FULL, p[i], s);
    }

    const int off[8] = {0, 8, 15, 21, 26, 30, 33, 35};
    float sq[KH];
    #pragma unroll
    for (int k = 0; k < KH; ++k) sq[k] = p[off[k]];

    float best = -3.4e38f;
    int bi = 0;
    #pragma unroll
    for (int k = 0; k < KH; ++k) {
        #pragma unroll
        for (int l = 0; l < KH; ++l) {
            const int kk = (k < l) ? k : l;
            const int ll = (k < l) ? l : k;
            const float d2 = (sq[k] + sq[l]) - 2.0f * p[off[kk] + (ll - kk)];
            if (d2 > best) { best = d2; bi = k * KH + l; }
        }
    }
    const int ui = bi >> 3, vi = bi & 7;

    if (lane == 0) g_pos[warp] = ui | (vi << 8);
    const float w = 1.0f / 13.0f;   // 1/(2K-3)
    if (lane < KH) {
        if (lane == ui)       atomicAdd(&g_deg[verts[ui]], 7.0f * w);
        else if (lane == vi)  atomicAdd(&g_deg[verts[vi]], 7.0f * w);
        else                  atomicAdd(&g_deg[verts[lane]], 2.0f * w);
    }
}

// ---------------- K3: dinv + out = Y*dinv (self term) ----------------
__global__ void k_self(float* __restrict__ out) {
    int i = blockIdx.x * blockDim.x + threadIdx.x;
    if (i >= NV * 32) return;
    const int n = i >> 5;
    const float d = rsqrtf(g_deg[n]);
    if ((i & 31) == 0) g_dinv[n] = d;
    float4 y = reinterpret_cast<const float4*>(g_Y)[i];
    reinterpret_cast<float4*>(out)[i] = make_float4(y.x * d, y.y * d, y.z * d, y.w * d);
}

// ---------------- K4: feature scatter (folded, v4 red atomics) ----------------
__global__ __launch_bounds__(256) void k_scatter(const int* __restrict__ vertex,
                                                 float* __restrict__ out) {
    const int warp = (blockIdx.x * 256 + threadIdx.x) >> 5;
    const int lane = threadIdx.x & 31;
    if (warp >= ME) return;
    const unsigned FULL = 0xffffffffu;

    int   vr = (lane < KH) ? vertex[warp * KH + lane] : 0;
    float dr = (lane < KH) ? g_dinv[vr] : 0.f;
    int verts[KH];
    float dk[KH];
    #pragma unroll
    for (int i = 0; i < KH; ++i) {
        verts[i] = __shfl_sync(FULL, vr, i);
        dk[i]    = __shfl_sync(FULL, dr, i);
    }

    const int pos = g_pos[warp];
    const int ui = pos & 0xff, vi = (pos >> 8) & 0xff;
    const int u = verts[ui], v = verts[vi];
    const float w = 1.0f / 13.0f;

    float4 yu = *reinterpret_cast<const float4*>(g_Y + (size_t)u * DD + lane * 4);
    float4 yv = *reinterpret_cast<const float4*>(g_Y + (size_t)v * DD + lane * 4);
    const float du = dk[ui], dv = dk[vi];
    const float4 xu = make_float4(yu.x * du, yu.y * du, yu.z * du, yu.w * du);
    const float4 xv = make_float4(yv.x * dv, yv.y * dv, yv.z * dv, yv.w * dv);

    const float tx = w * (xu.x + xv.x);
    const float ty = w * (xu.y + xv.y);
    const float tz = w * (xu.z + xv.z);
    const float tw = w * (xu.w + xv.w);

    float4 S = make_float4(0.f, 0.f, 0.f, 0.f);
    #pragma unroll
    for (int pidx = 0; pidx < KH; ++pidx) {
        if (pidx == ui || pidx == vi) continue;
        const int mv = verts[pidx];
        const float dm = dk[pidx];
        float4 ym = *reinterpret_cast<const float4*>(g_Y + (size_t)mv * DD + lane * 4);
        S.x += ym.x * dm; S.y += ym.y * dm; S.z += ym.z * dm; S.w += ym.w * dm;
        red4(out + (size_t)mv * DD + lane * 4, tx, ty, tz, tw);
    }
    red4(out + (size_t)u * DD + lane * 4,
         w * (xv.x + S.x), w * (xv.y + S.y), w * (xv.z + S.z), w * (xv.w + S.w));
    red4(out + (size_t)v * DD + lane * 4,
         w * (xu.x + S.x), w * (xu.y + S.y), w * (xu.z + S.z), w * (xu.w + S.w));
}

// ---------------- K5: out = relu(out * dinv) ----------------
__global__ void k_relu(float* __restrict__ out) {
    int i = blockIdx.x * blockDim.x + threadIdx.x;
    if (i >= NV * 32) return;
    const int n = i >> 5;
    const float d = g_dinv[n];
    float4 o = reinterpret_cast<float4*>(out)[i];
    o.x = fmaxf(o.x * d, 0.f);
    o.y = fmaxf(o.y * d, 0.f);
    o.z = fmaxf(o.z * d, 0.f);
    o.w = fmaxf(o.w * d, 0.f);
    reinterpret_cast<float4*>(out)[i] = o;
}

// ---------------- launch ----------------
extern "C" void kernel_launch(void* const* d_in, const int* in_sizes, int n_in,
                              void* d_out, int out_size) {
    const float* X      = (const float*)d_in[0];   // [N, 128]
    const int*   vertex = (const int*)  d_in[1];   // [M*8]
    const float* W      = (const float*)d_in[3];   // [128, 128]
    const float* b      = (const float*)d_in[4];   // [128]
    float* out = (float*)d_out;

    cudaFuncSetAttribute(k_gemm, cudaFuncAttributeMaxDynamicSharedMemorySize, SMEM_SZ);

    k_pre<<<(NV + 255) / 256, 256>>>(W);
    k_gemm<<<(NV + 127) / 128, 256, SMEM_SZ>>>(X, b);
    k_edges<<<(ME * 32 + 255) / 256, 256>>>(vertex);
    k_self<<<(NV * 32 + 255) / 256, 256>>>(out);
    k_scatter<<<(ME * 32 + 255) / 256, 256>>>(vertex, out);
    k_relu<<<(NV * 32 + 255) / 256, 256>>>(out);
}

// round 4
// speedup vs baseline: 1.2577x; 1.1719x over previous
#include <cuda_runtime.h>
#include <cuda_fp16.h>
#include <cstdint>

#define NV 100000      // vertices
#define ME 50000       // hyperedges
#define KH 8           // hyperedge size
#define DD 128         // feature dim
#define ASTRIDE 136    // smem A/stage row stride (halves / floats)

// ---------------- scratch (no allocs allowed) ----------------
__device__ float  g_Y  [(size_t)NV * DD];   // X@W + b
__device__ float  g_deg [NV];
__device__ int    g_pos[ME];                // ui | (vi<<8)
__device__ __half g_Wph[16384];             // W hi, mma B-fragment layout
__device__ __half g_Wpl[16384];             // W lo, mma B-fragment layout

__device__ __forceinline__ void red4(float* p, float a, float b, float c, float d) {
    asm volatile("red.global.add.v4.f32 [%0], {%1,%2,%3,%4};"
                 :: "l"(p), "f"(a), "f"(b), "f"(c), "f"(d) : "memory");
}
__device__ __forceinline__ uint32_t pk2(__half a, __half b) {
    __half2 t = __halves2half2(a, b);
    return *reinterpret_cast<uint32_t*>(&t);
}

// ---------------- K_pre: deg=1 ; pack W hi/lo ; zero out ----------------
__global__ void k_pre(const float* __restrict__ W, float4* __restrict__ out) {
    int t = blockIdx.x * blockDim.x + threadIdx.x;   // grid covers NV*32 = 3.2M
    out[t] = make_float4(0.f, 0.f, 0.f, 0.f);
    if (t < NV) g_deg[t] = 1.0f;
    if (t < 16384) {
        int k = t >> 7, n = t & 127;          // W[k][n]
        float w = W[t];
        __half wh = __float2half_rn(w);
        __half wl = __float2half_rn(w - __half2float(wh));
        int s = k >> 4, kr = k & 15;
        int r = kr >> 3;
        int lane = ((n & 7) << 2) | ((kr & 7) >> 1);
        int j = n >> 3;
        int idx = ((((s * 16 + j) * 32 + lane) * 2 + r) << 1) | (kr & 1);
        g_Wph[idx] = wh;
        g_Wpl[idx] = wl;
    }
}

// ---------------- K1: Y = X@W + b via fp16-split mma.sync, B in smem ----------------
#define SM_B   512
#define SM_A   (512 + 65536)
#define SMEM_SZ (SM_A + 128 * ASTRIDE * 2 * 2)

__global__ __launch_bounds__(256) void k_gemm(const float* __restrict__ X,
                                              const float* __restrict__ b) {
    extern __shared__ char smem[];
    float*  bsm   = reinterpret_cast<float*>(smem);              // 128 floats
    uint2*  Bsm   = reinterpret_cast<uint2*>(smem + SM_B);       // 64KB: hi[4096] lo[4096]
    __half* Ah    = reinterpret_cast<__half*>(smem + SM_A);
    __half* Al    = Ah + 128 * ASTRIDE;
    float*  stage = reinterpret_cast<float*>(smem + SM_A);       // epilogue alias

    const int tid  = threadIdx.x;
    const int row0 = blockIdx.x * 128;
    if (tid < 128) bsm[tid] = b[tid];

    // copy packed W hi+lo (64KB) into smem
    {
        const uint4* sh = reinterpret_cast<const uint4*>(g_Wph);
        const uint4* sl = reinterpret_cast<const uint4*>(g_Wpl);
        uint4* dst = reinterpret_cast<uint4*>(Bsm);
        #pragma unroll
        for (int i = 0; i < 8; ++i) {
            dst[tid + i * 256]        = sh[tid + i * 256];
            dst[2048 + tid + i * 256] = sl[tid + i * 256];
        }
    }

    // load X tile coalesced, split fp16 hi/lo into smem
    #pragma unroll
    for (int i = 0; i < 16; ++i) {
        int f4  = tid + i * 256;
        int row = f4 >> 5;
        int c   = f4 & 31;
        float4 x = make_float4(0.f, 0.f, 0.f, 0.f);
        if (row0 + row < NV)
            x = reinterpret_cast<const float4*>(X + (size_t)(row0 + row) * 128)[c];
        __half hx = __float2half_rn(x.x), hy = __float2half_rn(x.y);
        __half hz = __float2half_rn(x.z), hw = __float2half_rn(x.w);
        *reinterpret_cast<uint2*>(&Ah[row * ASTRIDE + c * 4]) =
            make_uint2(pk2(hx, hy), pk2(hz, hw));
        *reinterpret_cast<uint2*>(&Al[row * ASTRIDE + c * 4]) =
            make_uint2(pk2(__float2half_rn(x.x - __half2float(hx)),
                           __float2half_rn(x.y - __half2float(hy))),
                       pk2(__float2half_rn(x.z - __half2float(hz)),
                           __float2half_rn(x.w - __half2float(hw))));
    }
    __syncthreads();

    const int wid = tid >> 5, lane = tid & 31;
    const int m0 = wid * 16;
    const int rr = lane >> 2, kc = lane & 3;

    float acc[16][4];
    #pragma unroll
    for (int j = 0; j < 16; ++j)
        acc[j][0] = acc[j][1] = acc[j][2] = acc[j][3] = 0.f;

    #pragma unroll 1
    for (int pass = 0; pass < 3; ++pass) {
        const __half* A = (pass == 2) ? Al : Ah;
        const uint2*  B = Bsm + ((pass == 1) ? 4096 : 0);
        #pragma unroll
        for (int s = 0; s < 8; ++s) {
            const int ka = s * 16 + kc * 2;
            uint32_t a0 = *reinterpret_cast<const uint32_t*>(&A[(m0 + rr)     * ASTRIDE + ka]);
            uint32_t a1 = *reinterpret_cast<const uint32_t*>(&A[(m0 + rr + 8) * ASTRIDE + ka]);
            uint32_t a2 = *reinterpret_cast<const uint32_t*>(&A[(m0 + rr)     * ASTRIDE + ka + 8]);
            uint32_t a3 = *reinterpret_cast<const uint32_t*>(&A[(m0 + rr + 8) * ASTRIDE + ka + 8]);
            #pragma unroll
            for (int j = 0; j < 16; ++j) {
                uint2 bb = B[(s * 16 + j) * 32 + lane];
                asm volatile(
                    "mma.sync.aligned.m16n8k16.row.col.f32.f16.f16.f32 "
                    "{%0,%1,%2,%3}, {%4,%5,%6,%7}, {%8,%9}, {%0,%1,%2,%3};"
                    : "+f"(acc[j][0]), "+f"(acc[j][1]), "+f"(acc[j][2]), "+f"(acc[j][3])
                    : "r"(a0), "r"(a1), "r"(a2), "r"(a3), "r"(bb.x), "r"(bb.y));
            }
        }
    }
    __syncthreads();   // A dead; smem becomes stage

    #pragma unroll
    for (int j = 0; j < 16; ++j) {
        const int n0 = j * 8 + kc * 2;
        const float b0 = bsm[n0], b1 = bsm[n0 + 1];
        *reinterpret_cast<float2*>(&stage[(m0 + rr)     * ASTRIDE + n0]) =
            make_float2(acc[j][0] + b0, acc[j][1] + b1);
        *reinterpret_cast<float2*>(&stage[(m0 + rr + 8) * ASTRIDE + n0]) =
            make_float2(acc[j][2] + b0, acc[j][3] + b1);
    }
    __syncthreads();
    #pragma unroll
    for (int s2 = 0; s2 < 16; ++s2) {
        int f  = tid + s2 * 256;
        int r2 = f >> 5, c2 = f & 31;
        if (row0 + r2 < NV) {
            float4 v = *reinterpret_cast<const float4*>(&stage[r2 * ASTRIDE + c2 * 4]);
            *reinterpret_cast<float4*>(g_Y + (size_t)(row0 + r2) * 128 + c2 * 4) = v;
        }
    }
}

// ---------------- K2: per-hyperedge argmax pair + degree atomics ----------------
__global__ __launch_bounds__(256) void k_edges(const int* __restrict__ vertex) {
    const int warp = (blockIdx.x * 256 + threadIdx.x) >> 5;
    const int lane = threadIdx.x & 31;
    if (warp >= ME) return;
    const unsigned FULL = 0xffffffffu;

    int vr = (lane < KH) ? vertex[warp * KH + lane] : 0;
    int verts[KH];
    #pragma unroll
    for (int i = 0; i < KH; ++i) verts[i] = __shfl_sync(FULL, vr, i);

    float4 f[KH];
    #pragma unroll
    for (int k = 0; k < KH; ++k)
        f[k] = *reinterpret_cast<const float4*>(g_Y + (size_t)verts[k] * DD + lane * 4);

    float p[36];
    {
        int idx = 0;
        #pragma unroll
        for (int k = 0; k < KH; ++k)
            #pragma unroll
            for (int l = k; l < KH; ++l)
                p[idx++] = f[k].x * f[l].x + f[k].y * f[l].y +
                           f[k].z * f[l].z + f[k].w * f[l].w;
    }
    #pragma unroll
    for (int i = 0; i < 36; ++i) {
        #pragma unroll
        for (int s = 16; s > 0; s >>= 1)
            p[i] += __shfl_xor_sync(FULL, p[i], s);
    }

    const int off[8] = {0, 8, 15, 21, 26, 30, 33, 35};
    float sq[KH];
    #pragma unroll
    for (int k = 0; k < KH; ++k) sq[k] = p[off[k]];

    float best = -3.4e38f;
    int bi = 0;
    #pragma unroll
    for (int k = 0; k < KH; ++k) {
        #pragma unroll
        for (int l = 0; l < KH; ++l) {
            const int kk = (k < l) ? k : l;
            const int ll = (k < l) ? l : k;
            const float d2 = (sq[k] + sq[l]) - 2.0f * p[off[kk] + (ll - kk)];
            if (d2 > best) { best = d2; bi = k * KH + l; }
        }
    }
    const int ui = bi >> 3, vi = bi & 7;

    if (lane == 0) g_pos[warp] = ui | (vi << 8);
    const float w = 1.0f / 13.0f;   // 1/(2K-3)
    if (lane < KH) {
        if (lane == ui)       atomicAdd(&g_deg[verts[ui]], 7.0f * w);
        else if (lane == vi)  atomicAdd(&g_deg[verts[vi]], 7.0f * w);
        else                  atomicAdd(&g_deg[verts[lane]], 2.0f * w);
    }
}

// ---------------- K4: feature scatter into zeroed out (v4 red atomics) ----------------
__global__ __launch_bounds__(256) void k_scatter(const int* __restrict__ vertex,
                                                 float* __restrict__ out) {
    const int warp = (blockIdx.x * 256 + threadIdx.x) >> 5;
    const int lane = threadIdx.x & 31;
    if (warp >= ME) return;
    const unsigned FULL = 0xffffffffu;

    int   vr = (lane < KH) ? vertex[warp * KH + lane] : 0;
    float dr = (lane < KH) ? rsqrtf(g_deg[vr]) : 0.f;
    int verts[KH];
    float dk[KH];
    #pragma unroll
    for (int i = 0; i < KH; ++i) {
        verts[i] = __shfl_sync(FULL, vr, i);
        dk[i]    = __shfl_sync(FULL, dr, i);
    }

    const int pos = g_pos[warp];
    const int ui = pos & 0xff, vi = (pos >> 8) & 0xff;
    const int u = verts[ui], v = verts[vi];
    const float w = 1.0f / 13.0f;

    float4 yu = *reinterpret_cast<const float4*>(g_Y + (size_t)u * DD + lane * 4);
    float4 yv = *reinterpret_cast<const float4*>(g_Y + (size_t)v * DD + lane * 4);
    const float du = dk[ui], dv = dk[vi];
    const float4 xu = make_float4(yu.x * du, yu.y * du, yu.z * du, yu.w * du);
    const float4 xv = make_float4(yv.x * dv, yv.y * dv, yv.z * dv, yv.w * dv);

    const float tx = w * (xu.x + xv.x);
    const float ty = w * (xu.y + xv.y);
    const float tz = w * (xu.z + xv.z);
    const float tw = w * (xu.w + xv.w);

    float4 S = make_float4(0.f, 0.f, 0.f, 0.f);
    #pragma unroll
    for (int pidx = 0; pidx < KH; ++pidx) {
        if (pidx == ui || pidx == vi) continue;
        const int mv = verts[pidx];
        const float dm = dk[pidx];
        float4 ym = *reinterpret_cast<const float4*>(g_Y + (size_t)mv * DD + lane * 4);
        S.x += ym.x * dm; S.y += ym.y * dm; S.z += ym.z * dm; S.w += ym.w * dm;
        red4(out + (size_t)mv * DD + lane * 4, tx, ty, tz, tw);
    }
    red4(out + (size_t)u * DD + lane * 4,
         w * (xv.x + S.x), w * (xv.y + S.y), w * (xv.z + S.z), w * (xv.w + S.w));
    red4(out + (size_t)v * DD + lane * 4,
         w * (xu.x + S.x), w * (xu.y + S.y), w * (xu.z + S.z), w * (xu.w + S.w));
}

// ---------------- K5: out = relu(dinv*(dinv*Y + out)) ----------------
__global__ void k_fin(float* __restrict__ out) {
    int i = blockIdx.x * blockDim.x + threadIdx.x;   // float4 idx, < NV*32
    const int n = i >> 5;
    const float d = rsqrtf(g_deg[n]);
    float4 y = reinterpret_cast<const float4*>(g_Y)[i];
    float4 o = reinterpret_cast<float4*>(out)[i];
    o.x = fmaxf(d * (d * y.x + o.x), 0.f);
    o.y = fmaxf(d * (d * y.y + o.y), 0.f);
    o.z = fmaxf(d * (d * y.z + o.z), 0.f);
    o.w = fmaxf(d * (d * y.w + o.w), 0.f);
    reinterpret_cast<float4*>(out)[i] = o;
}

// ---------------- launch ----------------
extern "C" void kernel_launch(void* const* d_in, const int* in_sizes, int n_in,
                              void* d_out, int out_size) {
    const float* X      = (const float*)d_in[0];   // [N, 128]
    const int*   vertex = (const int*)  d_in[1];   // [M*8]
    const float* W      = (const float*)d_in[3];   // [128, 128]
    const float* b      = (const float*)d_in[4];   // [128]
    float* out = (float*)d_out;

    cudaFuncSetAttribute(k_gemm, cudaFuncAttributeMaxDynamicSharedMemorySize, SMEM_SZ);

    k_pre<<<NV * 32 / 256, 256>>>(W, (float4*)out);         // 12500 blocks
    k_gemm<<<(NV + 127) / 128, 256, SMEM_SZ>>>(X, b);
    k_edges<<<(ME * 32 + 255) / 256, 256>>>(vertex);
    k_scatter<<<(ME * 32 + 255) / 256, 256>>>(vertex, out);
    k_fin<<<NV * 32 / 256, 256>>>(out);
}

// round 5
// speedup vs baseline: 1.3986x; 1.1121x over previous
#include <cuda_runtime.h>
#include <cuda_fp16.h>
#include <cstdint>

#define NV 100000      // vertices
#define ME 50000       // hyperedges
#define KH 8           // hyperedge size
#define DD 128         // feature dim
#define ASTRIDE 136    // smem A/stage row stride (halves / floats)

// ---------------- scratch (no allocs allowed) ----------------
__device__ float  g_Y  [(size_t)NV * DD];   // X@W + b
__device__ float  g_deg [NV];
__device__ int    g_pos[ME];                // ui | (vi<<8)
__device__ __half g_Wph[16384];             // W hi, mma B-fragment layout
__device__ __half g_Wpl[16384];             // W lo, mma B-fragment layout

__device__ __forceinline__ void red4(float* p, float a, float b, float c, float d) {
    asm volatile("red.global.add.v4.f32 [%0], {%1,%2,%3,%4};"
                 :: "l"(p), "f"(a), "f"(b), "f"(c), "f"(d) : "memory");
}
__device__ __forceinline__ uint32_t pk2(__half a, __half b) {
    __half2 t = __halves2half2(a, b);
    return *reinterpret_cast<uint32_t*>(&t);
}
__device__ __forceinline__ uint32_t pkf2(float a, float b) {
    __half2 t = __floats2half2_rn(a, b);
    return *reinterpret_cast<uint32_t*>(&t);
}

// ---------------- K_pre: deg=1 ; pack W hi/lo ; zero out ----------------
__global__ void k_pre(const float* __restrict__ W, float4* __restrict__ out) {
    int t = blockIdx.x * blockDim.x + threadIdx.x;   // grid covers NV*32 = 3.2M
    out[t] = make_float4(0.f, 0.f, 0.f, 0.f);
    if (t < NV) g_deg[t] = 1.0f;
    if (t < 16384) {
        int k = t >> 7, n = t & 127;          // W[k][n]
        float w = W[t];
        __half wh = __float2half_rn(w);
        __half wl = __float2half_rn(w - __half2float(wh));
        int s = k >> 4, kr = k & 15;
        int r = kr >> 3;
        int lane = ((n & 7) << 2) | ((kr & 7) >> 1);
        int j = n >> 3;
        int idx = ((((s * 16 + j) * 32 + lane) * 2 + r) << 1) | (kr & 1);
        g_Wph[idx] = wh;
        g_Wpl[idx] = wl;
    }
}

// ---------------- K1: Y = X@W + b via fp16-split mma.sync, B in smem ----------------
#define SM_B   512
#define SM_A   (512 + 65536)
#define SMEM_SZ (SM_A + 128 * ASTRIDE * 2 * 2)

__global__ __launch_bounds__(256) void k_gemm(const float* __restrict__ X,
                                              const float* __restrict__ b) {
    extern __shared__ char smem[];
    float*  bsm   = reinterpret_cast<float*>(smem);              // 128 floats
    uint2*  Bsm   = reinterpret_cast<uint2*>(smem + SM_B);       // 64KB: hi[4096] lo[4096]
    __half* Ah    = reinterpret_cast<__half*>(smem + SM_A);
    __half* Al    = Ah + 128 * ASTRIDE;
    float*  stage = reinterpret_cast<float*>(smem + SM_A);       // epilogue alias

    const int tid  = threadIdx.x;
    const int row0 = blockIdx.x * 128;
    if (tid < 128) bsm[tid] = b[tid];

    // copy packed W hi+lo (64KB) into smem
    {
        const uint4* sh = reinterpret_cast<const uint4*>(g_Wph);
        const uint4* sl = reinterpret_cast<const uint4*>(g_Wpl);
        uint4* dst = reinterpret_cast<uint4*>(Bsm);
        #pragma unroll
        for (int i = 0; i < 8; ++i) {
            dst[tid + i * 256]        = sh[tid + i * 256];
            dst[2048 + tid + i * 256] = sl[tid + i * 256];
        }
    }

    // load X tile coalesced, split fp16 hi/lo into smem
    #pragma unroll
    for (int i = 0; i < 16; ++i) {
        int f4  = tid + i * 256;
        int row = f4 >> 5;
        int c   = f4 & 31;
        float4 x = make_float4(0.f, 0.f, 0.f, 0.f);
        if (row0 + row < NV)
            x = reinterpret_cast<const float4*>(X + (size_t)(row0 + row) * 128)[c];
        __half hx = __float2half_rn(x.x), hy = __float2half_rn(x.y);
        __half hz = __float2half_rn(x.z), hw = __float2half_rn(x.w);
        *reinterpret_cast<uint2*>(&Ah[row * ASTRIDE + c * 4]) =
            make_uint2(pk2(hx, hy), pk2(hz, hw));
        *reinterpret_cast<uint2*>(&Al[row * ASTRIDE + c * 4]) =
            make_uint2(pk2(__float2half_rn(x.x - __half2float(hx)),
                           __float2half_rn(x.y - __half2float(hy))),
                       pk2(__float2half_rn(x.z - __half2float(hz)),
                           __float2half_rn(x.w - __half2float(hw))));
    }
    __syncthreads();

    const int wid = tid >> 5, lane = tid & 31;
    const int m0 = wid * 16;
    const int rr = lane >> 2, kc = lane & 3;

    float acc[16][4];
    #pragma unroll
    for (int j = 0; j < 16; ++j)
        acc[j][0] = acc[j][1] = acc[j][2] = acc[j][3] = 0.f;

    #pragma unroll 1
    for (int pass = 0; pass < 3; ++pass) {
        const __half* A = (pass == 2) ? Al : Ah;
        const uint2*  B = Bsm + ((pass == 1) ? 4096 : 0);
        #pragma unroll
        for (int s = 0; s < 8; ++s) {
            const int ka = s * 16 + kc * 2;
            uint32_t a0 = *reinterpret_cast<const uint32_t*>(&A[(m0 + rr)     * ASTRIDE + ka]);
            uint32_t a1 = *reinterpret_cast<const uint32_t*>(&A[(m0 + rr + 8) * ASTRIDE + ka]);
            uint32_t a2 = *reinterpret_cast<const uint32_t*>(&A[(m0 + rr)     * ASTRIDE + ka + 8]);
            uint32_t a3 = *reinterpret_cast<const uint32_t*>(&A[(m0 + rr + 8) * ASTRIDE + ka + 8]);
            #pragma unroll
            for (int j = 0; j < 16; ++j) {
                uint2 bb = B[(s * 16 + j) * 32 + lane];
                asm volatile(
                    "mma.sync.aligned.m16n8k16.row.col.f32.f16.f16.f32 "
                    "{%0,%1,%2,%3}, {%4,%5,%6,%7}, {%8,%9}, {%0,%1,%2,%3};"
                    : "+f"(acc[j][0]), "+f"(acc[j][1]), "+f"(acc[j][2]), "+f"(acc[j][3])
                    : "r"(a0), "r"(a1), "r"(a2), "r"(a3), "r"(bb.x), "r"(bb.y));
            }
        }
    }
    __syncthreads();   // A dead; smem becomes stage

    #pragma unroll
    for (int j = 0; j < 16; ++j) {
        const int n0 = j * 8 + kc * 2;
        const float b0 = bsm[n0], b1 = bsm[n0 + 1];
        *reinterpret_cast<float2*>(&stage[(m0 + rr)     * ASTRIDE + n0]) =
            make_float2(acc[j][0] + b0, acc[j][1] + b1);
        *reinterpret_cast<float2*>(&stage[(m0 + rr + 8) * ASTRIDE + n0]) =
            make_float2(acc[j][2] + b0, acc[j][3] + b1);
    }
    __syncthreads();
    #pragma unroll
    for (int s2 = 0; s2 < 16; ++s2) {
        int f  = tid + s2 * 256;
        int r2 = f >> 5, c2 = f & 31;
        if (row0 + r2 < NV) {
            float4 v = *reinterpret_cast<const float4*>(&stage[r2 * ASTRIDE + c2 * 4]);
            *reinterpret_cast<float4*>(g_Y + (size_t)(row0 + r2) * 128 + c2 * 4) = v;
        }
    }
}

// ---------------- K2: per-hyperedge argmax pair via mma Gram + degree atomics ----------------
__global__ __launch_bounds__(256) void k_edges(const int* __restrict__ vertex) {
    __shared__ __half sF[8][2][8][ASTRIDE];   // [warp][hi/lo][row][dim]  ~34.8KB
    const int wip  = threadIdx.x >> 5;
    const int warp = blockIdx.x * 8 + wip;
    const int lane = threadIdx.x & 31;
    if (warp >= ME) return;
    const unsigned FULL = 0xffffffffu;

    int vr = (lane < KH) ? vertex[warp * KH + lane] : 0;
    int verts[KH];
    #pragma unroll
    for (int i = 0; i < KH; ++i) verts[i] = __shfl_sync(FULL, vr, i);

    // gather 8 rows of Y (lane: dims 4l..4l+3), split fp16 hi/lo into smem
    #pragma unroll
    for (int k = 0; k < KH; ++k) {
        float4 y = *reinterpret_cast<const float4*>(g_Y + (size_t)verts[k] * DD + lane * 4);
        uint32_t h01 = pkf2(y.x, y.y), h23 = pkf2(y.z, y.w);
        float2 b01 = __half22float2(*reinterpret_cast<__half2*>(&h01));
        float2 b23 = __half22float2(*reinterpret_cast<__half2*>(&h23));
        *reinterpret_cast<uint2*>(&sF[wip][0][k][lane * 4]) = make_uint2(h01, h23);
        *reinterpret_cast<uint2*>(&sF[wip][1][k][lane * 4]) =
            make_uint2(pkf2(y.x - b01.x, y.y - b01.y), pkf2(y.z - b23.x, y.w - b23.y));
    }
    __syncwarp();

    // Gram G = F F^T via fp16-split mma (A-frag == B-frag for same lane)
    const int rr = lane >> 2, kc = lane & 3;
    float c0 = 0.f, c1 = 0.f, c2 = 0.f, c3 = 0.f;
    #pragma unroll
    for (int s = 0; s < 8; ++s) {
        const int ka = s * 16 + kc * 2;
        uint32_t h0 = *reinterpret_cast<const uint32_t*>(&sF[wip][0][rr][ka]);
        uint32_t h1 = *reinterpret_cast<const uint32_t*>(&sF[wip][0][rr][ka + 8]);
        uint32_t l0 = *reinterpret_cast<const uint32_t*>(&sF[wip][1][rr][ka]);
        uint32_t l1 = *reinterpret_cast<const uint32_t*>(&sF[wip][1][rr][ka + 8]);
        asm volatile("mma.sync.aligned.m16n8k16.row.col.f32.f16.f16.f32 "
            "{%0,%1,%2,%3}, {%4,%5,%6,%7}, {%8,%9}, {%0,%1,%2,%3};"
            : "+f"(c0), "+f"(c1), "+f"(c2), "+f"(c3)
            : "r"(h0), "r"(0u), "r"(h1), "r"(0u), "r"(h0), "r"(h1));
        asm volatile("mma.sync.aligned.m16n8k16.row.col.f32.f16.f16.f32 "
            "{%0,%1,%2,%3}, {%4,%5,%6,%7}, {%8,%9}, {%0,%1,%2,%3};"
            : "+f"(c0), "+f"(c1), "+f"(c2), "+f"(c3)
            : "r"(h0), "r"(0u), "r"(h1), "r"(0u), "r"(l0), "r"(l1));
        asm volatile("mma.sync.aligned.m16n8k16.row.col.f32.f16.f16.f32 "
            "{%0,%1,%2,%3}, {%4,%5,%6,%7}, {%8,%9}, {%0,%1,%2,%3};"
            : "+f"(c0), "+f"(c1), "+f"(c2), "+f"(c3)
            : "r"(l0), "r"(0u), "r"(l1), "r"(0u), "r"(h0), "r"(h1));
    }
    // lane (rr,kc) holds G[rr][2kc] (c0) and G[rr][2kc+1] (c1); c2/c3 garbage rows

    // sq broadcasts: diag G[k][k] lives on lane k*4 + (k>>1), in c0 if k even else c1
    const float mydiag = (rr & 1) ? c1 : c0;
    const float sq_r  = __shfl_sync(FULL, mydiag, rr * 4 + (rr >> 1));
    const float sq_c0 = __shfl_sync(FULL, mydiag, 9 * kc);
    const float sq_c1 = __shfl_sync(FULL, mydiag, 9 * kc + 4);

    float e0 = (sq_r + sq_c0) - 2.0f * c0;
    float e1 = (sq_r + sq_c1) - 2.0f * c1;
    int   i0 = rr * 8 + kc * 2;
    float bv; int bi;
    if (e1 > e0) { bv = e1; bi = i0 + 1; } else { bv = e0; bi = i0; }
    #pragma unroll
    for (int s = 16; s > 0; s >>= 1) {
        float ov = __shfl_xor_sync(FULL, bv, s);
        int   oi = __shfl_xor_sync(FULL, bi, s);
        if (ov > bv || (ov == bv && oi < bi)) { bv = ov; bi = oi; }
    }
    const int ui = bi >> 3, vi = bi & 7;

    if (lane == 0) g_pos[warp] = ui | (vi << 8);
    const float w = 1.0f / 13.0f;   // 1/(2K-3)
    if (lane < KH) {
        if (lane == ui)       atomicAdd(&g_deg[verts[ui]], 7.0f * w);
        else if (lane == vi)  atomicAdd(&g_deg[verts[vi]], 7.0f * w);
        else                  atomicAdd(&g_deg[verts[lane]], 2.0f * w);
    }
}

// ---------------- K4: feature scatter into zeroed out (v4 red atomics) ----------------
__global__ __launch_bounds__(256) void k_scatter(const int* __restrict__ vertex,
                                                 float* __restrict__ out) {
    const int warp = (blockIdx.x * 256 + threadIdx.x) >> 5;
    const int lane = threadIdx.x & 31;
    if (warp >= ME) return;
    const unsigned FULL = 0xffffffffu;

    int   vr = (lane < KH) ? vertex[warp * KH + lane] : 0;
    float dr = (lane < KH) ? rsqrtf(g_deg[vr]) : 0.f;
    int verts[KH];
    float dk[KH];
    #pragma unroll
    for (int i = 0; i < KH; ++i) {
        verts[i] = __shfl_sync(FULL, vr, i);
        dk[i]    = __shfl_sync(FULL, dr, i);
    }

    const int pos = g_pos[warp];
    const int ui = pos & 0xff, vi = (pos >> 8) & 0xff;
    const int u = verts[ui], v = verts[vi];
    const float w = 1.0f / 13.0f;

    float4 yu = *reinterpret_cast<const float4*>(g_Y + (size_t)u * DD + lane * 4);
    float4 yv = *reinterpret_cast<const float4*>(g_Y + (size_t)v * DD + lane * 4);
    const float du = dk[ui], dv = dk[vi];
    const float4 xu = make_float4(yu.x * du, yu.y * du, yu.z * du, yu.w * du);
    const float4 xv = make_float4(yv.x * dv, yv.y * dv, yv.z * dv, yv.w * dv);

    const float tx = w * (xu.x + xv.x);
    const float ty = w * (xu.y + xv.y);
    const float tz = w * (xu.z + xv.z);
    const float tw = w * (xu.w + xv.w);

    float4 S = make_float4(0.f, 0.f, 0.f, 0.f);
    #pragma unroll
    for (int pidx = 0; pidx < KH; ++pidx) {
        if (pidx == ui || pidx == vi) continue;
        const int mv = verts[pidx];
        const float dm = dk[pidx];
        float4 ym = *reinterpret_cast<const float4*>(g_Y + (size_t)mv * DD + lane * 4);
        S.x += ym.x * dm; S.y += ym.y * dm; S.z += ym.z * dm; S.w += ym.w * dm;
        red4(out + (size_t)mv * DD + lane * 4, tx, ty, tz, tw);
    }
    red4(out + (size_t)u * DD + lane * 4,
         w * (xv.x + S.x), w * (xv.y + S.y), w * (xv.z + S.z), w * (xv.w + S.w));
    red4(out + (size_t)v * DD + lane * 4,
         w * (xu.x + S.x), w * (xu.y + S.y), w * (xu.z + S.z), w * (xu.w + S.w));
}

// ---------------- K5: out = relu(dinv*(dinv*Y + out)) ----------------
__global__ void k_fin(float* __restrict__ out) {
    int i = blockIdx.x * blockDim.x + threadIdx.x;   // float4 idx, < NV*32
    const int n = i >> 5;
    const float d = rsqrtf(g_deg[n]);
    float4 y = reinterpret_cast<const float4*>(g_Y)[i];
    float4 o = reinterpret_cast<float4*>(out)[i];
    o.x = fmaxf(d * (d * y.x + o.x), 0.f);
    o.y = fmaxf(d * (d * y.y + o.y), 0.f);
    o.z = fmaxf(d * (d * y.z + o.z), 0.f);
    o.w = fmaxf(d * (d * y.w + o.w), 0.f);
    reinterpret_cast<float4*>(out)[i] = o;
}

// ---------------- launch ----------------
extern "C" void kernel_launch(void* const* d_in, const int* in_sizes, int n_in,
                              void* d_out, int out_size) {
    const float* X      = (const float*)d_in[0];   // [N, 128]
    const int*   vertex = (const int*)  d_in[1];   // [M*8]
    const float* W      = (const float*)d_in[3];   // [128, 128]
    const float* b      = (const float*)d_in[4];   // [128]
    float* out = (float*)d_out;

    cudaFuncSetAttribute(k_gemm, cudaFuncAttributeMaxDynamicSharedMemorySize, SMEM_SZ);

    k_pre<<<NV * 32 / 256, 256>>>(W, (float4*)out);         // 12500 blocks
    k_gemm<<<(NV + 127) / 128, 256, SMEM_SZ>>>(X, b);
    k_edges<<<(ME + 7) / 8, 256>>>(vertex);
    k_scatter<<<(ME * 32 + 255) / 256, 256>>>(vertex, out);
    k_fin<<<NV * 32 / 256, 256>>>(out);
}